// round 10
// baseline (speedup 1.0000x reference)
#include <cuda_runtime.h>
#include <cuda_fp16.h>

#define NUP1    100001            // NUM_USERS + 1
#define NROWS   200001            // total nodes
#define NNZE    2000000
#define NF4     (NROWS * 16)      // 16 x half4 per node = 64 scalars
#define SCAN_B  1024
#define NB      ((NROWS + SCAN_B - 1) / SCAN_B)   // 196

// ---- static device scratch ----
__device__ uint2  g_A16[NF4];     // layer 0 fp16 (half4 packed)
__device__ uint2  g_B16[NF4];     // layer 1 fp16
__device__ uint2  g_C16[NF4];     // layer 2 fp16

__device__ int   g_cnt[NROWS];    // zero at entry; scan self-clears
__device__ int   g_rank[NNZE];    // per-edge rank within its row
__device__ int   g_ptr[NROWS + 1];
__device__ uint2 g_edge[NNZE];    // (col*128 byte offset, fp32 val bits)
__device__ volatile unsigned long long g_look[NB];  // cleared by scatter

__device__ __forceinline__ uint2 pack_half4(float2 a, float2 b) {
    __half2 h0 = __floats2half2_rn(a.x, a.y);
    __half2 h1 = __floats2half2_rn(b.x, b.y);
    return make_uint2(*(unsigned*)&h0, *(unsigned*)&h1);
}
__device__ __forceinline__ void unpack_half4(uint2 u, float2& a, float2& b) {
    a = __half22float2(*(__half2*)&u.x);
    b = __half22float2(*(__half2*)&u.y);
}

// init fp16 mirror of embeddings AND histogram+rank (fused).
__global__ void init_kernel(const float4* __restrict__ user4,
                            const float4* __restrict__ item4,
                            const int* __restrict__ rows, int nnz) {
    int i = blockIdx.x * blockDim.x + threadIdx.x;
    if (i < nnz) g_rank[i] = atomicAdd(&g_cnt[rows[i]], 1);
    if (i >= NF4) return;
    float4 v = (i < NUP1 * 16) ? __ldg(&user4[i])
                               : __ldg(&item4[i - NUP1 * 16 + 16]);
    g_A16[i] = pack_half4(make_float2(v.x, v.y), make_float2(v.z, v.w));
}

// Single-pass decoupled-lookback scan -> g_ptr; self-clears g_cnt.
__global__ void scan_kernel() {
    int t = threadIdx.x, b = blockIdx.x;
    int lane = t & 31, wid = t >> 5;
    int gid = b * SCAN_B + t;

    int cnt = (gid < NROWS) ? g_cnt[gid] : 0;

    int incl = cnt;
    #pragma unroll
    for (int o = 1; o < 32; o <<= 1) {
        int n = __shfl_up_sync(0xffffffffu, incl, o);
        if (lane >= o) incl += n;
    }
    __shared__ int wsum[32];
    __shared__ int s_excl;
    if (lane == 31) wsum[wid] = incl;
    __syncthreads();
    if (wid == 0) {
        int v = wsum[lane];
        #pragma unroll
        for (int o = 1; o < 32; o <<= 1) {
            int n = __shfl_up_sync(0xffffffffu, v, o);
            if (lane >= o) v += n;
        }
        wsum[lane] = v;
    }
    __syncthreads();
    int block_incl = incl + (wid ? wsum[wid - 1] : 0);
    int total = wsum[31];

    if (t == 0) {
        if (b == 0) { g_look[0] = (2ull << 32) | (unsigned)total; s_excl = 0; }
        else          g_look[b] = (1ull << 32) | (unsigned)total;
    }
    if (b > 0 && wid == 0) {
        int excl = 0;
        int idx = b - 1;
        while (true) {
            int look = idx - lane;
            unsigned long long w; int st;
            do {
                w = g_look[look < 0 ? 0 : look];
                st = (look < 0) ? 2 : (int)(w >> 32);
            } while (__any_sync(0xffffffffu, st == 0));
            int val = (look < 0) ? 0 : (int)(unsigned)w;
            unsigned pm = __ballot_sync(0xffffffffu, (look >= 0) && st == 2);
            int contrib;
            if (pm) {
                int plane = __ffs(pm) - 1;
                contrib = (lane <= plane) ? val : 0;
            } else {
                contrib = val;
            }
            #pragma unroll
            for (int o = 16; o; o >>= 1)
                contrib += __shfl_down_sync(0xffffffffu, contrib, o);
            contrib = __shfl_sync(0xffffffffu, contrib, 0);
            excl += contrib;
            if (pm) break;
            idx -= 32;
        }
        if (lane == 0) {
            g_look[b] = (2ull << 32) | (unsigned)(excl + total);
            s_excl = excl;
        }
    }
    __syncthreads();
    if (gid < NROWS) {
        int ex = s_excl + block_incl - cnt;
        g_ptr[gid] = ex;
        g_cnt[gid] = 0;                        // self-clean for next replay
        if (gid == NROWS - 1) g_ptr[NROWS] = ex + cnt;
    }
}

// Atomic-free bucket; stores PRE-SCALED col byte offset. Clears g_look.
__global__ void scatter_kernel(const int* __restrict__ rows,
                               const int* __restrict__ cols,
                               const float* __restrict__ vals, int nnz) {
    int e = blockIdx.x * blockDim.x + threadIdx.x;
    if (e < NB) g_look[e] = 0ull;
    if (e >= nnz) return;
    int pos = g_ptr[rows[e]] + g_rank[e];
    g_edge[pos] = make_uint2((unsigned)cols[e] * 128u,
                             (unsigned)__float_as_int(vals[e]));
}

// Half-warp per row: 16 lanes x half4 (8B) = one 128B row.
// xb = buffer base + l15*8 (lane byte offset); gather addr = xb + edge.x.
__device__ __forceinline__ void row_spmv(const char* __restrict__ xb,
                                         int s, int e,
                                         float2& s0, float2& s1) {
    s0 = make_float2(0.f, 0.f);
    s1 = make_float2(0.f, 0.f);
    for (int j = s; j < e; j += 4) {
        uint2 e0 = __ldg(&g_edge[j]);
        uint2 e1 = (j + 1 < e) ? __ldg(&g_edge[j + 1]) : make_uint2(0u, 0u);
        uint2 e2 = (j + 2 < e) ? __ldg(&g_edge[j + 2]) : make_uint2(0u, 0u);
        uint2 e3 = (j + 3 < e) ? __ldg(&g_edge[j + 3]) : make_uint2(0u, 0u);
        uint2 g0 = __ldg((const uint2*)(xb + e0.x));
        uint2 g1 = __ldg((const uint2*)(xb + e1.x));
        uint2 g2 = __ldg((const uint2*)(xb + e2.x));
        uint2 g3 = __ldg((const uint2*)(xb + e3.x));
        float v0 = __uint_as_float(e0.y);
        float v1 = __uint_as_float(e1.y);
        float v2 = __uint_as_float(e2.y);
        float v3 = __uint_as_float(e3.y);
        float2 a, b;
        unpack_half4(g0, a, b);
        s0.x = fmaf(v0, a.x, s0.x); s0.y = fmaf(v0, a.y, s0.y);
        s1.x = fmaf(v0, b.x, s1.x); s1.y = fmaf(v0, b.y, s1.y);
        unpack_half4(g1, a, b);
        s0.x = fmaf(v1, a.x, s0.x); s0.y = fmaf(v1, a.y, s0.y);
        s1.x = fmaf(v1, b.x, s1.x); s1.y = fmaf(v1, b.y, s1.y);
        unpack_half4(g2, a, b);
        s0.x = fmaf(v2, a.x, s0.x); s0.y = fmaf(v2, a.y, s0.y);
        s1.x = fmaf(v2, b.x, s1.x); s1.y = fmaf(v2, b.y, s1.y);
        unpack_half4(g3, a, b);
        s0.x = fmaf(v3, a.x, s0.x); s0.y = fmaf(v3, a.y, s0.y);
        s1.x = fmaf(v3, b.x, s1.x); s1.y = fmaf(v3, b.y, s1.y);
    }
}

__global__ void spmm_mid(int layer) {
    int warp = (blockIdx.x * blockDim.x + threadIdx.x) >> 5;
    int lane = threadIdx.x & 31;
    int row  = warp * 2 + (lane >> 4);
    if (row >= NROWS) return;
    int l15 = lane & 15;
    const char* xb = (const char*)((layer == 0) ? g_A16 : g_B16) + l15 * 8;
    uint2* __restrict__ y = (layer == 0) ? g_B16 : g_C16;
    float2 s0, s1;
    row_spmv(xb, g_ptr[row], g_ptr[row + 1], s0, s1);
    y[(size_t)row * 16 + l15] = pack_half4(s0, s1);
}

__global__ void spmm_final(const float4* __restrict__ user4,
                           const float4* __restrict__ item4,
                           float4* __restrict__ out) {
    int warp = (blockIdx.x * blockDim.x + threadIdx.x) >> 5;
    int lane = threadIdx.x & 31;
    int row  = warp * 2 + (lane >> 4);
    if (row >= NROWS) return;
    int l15 = lane & 15;
    const char* xb = (const char*)g_C16 + l15 * 8;
    float2 s0, s1;
    row_spmv(xb, g_ptr[row], g_ptr[row + 1], s0, s1);
    size_t o = (size_t)row * 16 + l15;
    // layer-0 fp32 directly from inputs (no staging copy)
    float4 a = (row < NUP1) ? __ldg(&user4[o])
                            : __ldg(&item4[(size_t)(row - NUP1 + 1) * 16 + l15]);
    float2 b0, b1, c0, c1;
    unpack_half4(g_B16[o], b0, b1);
    unpack_half4(g_C16[o], c0, c1);
    int outrow = (row < NUP1) ? row : row + 1;
    out[(size_t)outrow * 16 + l15] =
        make_float4((a.x + b0.x + c0.x + s0.x) * 0.25f,
                    (a.y + b0.y + c0.y + s0.y) * 0.25f,
                    (a.z + b1.x + c1.x + s1.x) * 0.25f,
                    (a.w + b1.y + c1.y + s1.y) * 0.25f);
    if (row == 0)
        out[(size_t)NUP1 * 16 + l15] = make_float4(0.f, 0.f, 0.f, 0.f);
}

extern "C" void kernel_launch(void* const* d_in, const int* in_sizes, int n_in,
                              void* d_out, int out_size) {
    const float4* user4 = (const float4*)d_in[0];
    const float4* item4 = (const float4*)d_in[1];
    const int*    rows  = (const int*)d_in[2];
    const int*    cols  = (const int*)d_in[3];
    const float*  vals  = (const float*)d_in[4];
    float4*       out   = (float4*)d_out;

    const int nnz = in_sizes[2];
    const int TB = 256;

    const int gInit = (NF4 + TB - 1) / TB;     // NF4 > NNZE, covers both
    const int gEdge = (nnz + TB - 1) / TB;
    const int nWarp = (NROWS + 1) / 2;
    const int gSpmm = (nWarp * 32 + TB - 1) / TB;

    init_kernel<<<gInit, TB>>>(user4, item4, rows, nnz);   // 0: init + hist/rank
    scan_kernel<<<NB, SCAN_B>>>();                         // 1
    scatter_kernel<<<gEdge, TB>>>(rows, cols, vals, nnz);  // 2 (atomic-free)
    spmm_mid<<<gSpmm, TB>>>(0);                            // 3  <- ncu lands here
    spmm_mid<<<gSpmm, TB>>>(1);                            // 4
    spmm_final<<<gSpmm, TB>>>(user4, item4, out);          // 5
}

// round 11
// speedup vs baseline: 1.1282x; 1.1282x over previous
#include <cuda_runtime.h>
#include <cuda_fp16.h>

#define NUP1    100001            // NUM_USERS + 1
#define NROWS   200001            // total nodes
#define NNZE    2000000
#define NF4     (NROWS * 16)      // 16 x half4 per node = 64 scalars
#define SCAN_B  1024
#define NB      ((NROWS + SCAN_B - 1) / SCAN_B)   // 196

// ---- static device scratch ----
__device__ uint2  g_A16[NF4];     // layer 0 fp16 (half4 packed)
__device__ uint2  g_B16[NF4];     // layer 1 fp16
__device__ uint2  g_C16[NF4];     // layer 2 fp16

__device__ int   g_cnt[NROWS];    // zero at entry; scan self-clears
__device__ int   g_rank[NNZE];    // per-edge rank within its row
__device__ int   g_ptr[NROWS + 1];
__device__ uint2 g_edge[NNZE];    // (col, half2(v,v) bits)
__device__ volatile unsigned long long g_look[NB];  // cleared by scatter

__device__ __forceinline__ uint2 pack_half4(float2 a, float2 b) {
    __half2 h0 = __floats2half2_rn(a.x, a.y);
    __half2 h1 = __floats2half2_rn(b.x, b.y);
    return make_uint2(*(unsigned*)&h0, *(unsigned*)&h1);
}
__device__ __forceinline__ void unpack_half4(uint2 u, float2& a, float2& b) {
    a = __half22float2(*(__half2*)&u.x);
    b = __half22float2(*(__half2*)&u.y);
}

// init fp16 mirror of embeddings AND histogram+rank (fused).
__global__ void init_kernel(const float4* __restrict__ user4,
                            const float4* __restrict__ item4,
                            const int* __restrict__ rows, int nnz) {
    int i = blockIdx.x * blockDim.x + threadIdx.x;
    if (i < nnz) g_rank[i] = atomicAdd(&g_cnt[rows[i]], 1);
    if (i >= NF4) return;
    float4 v = (i < NUP1 * 16) ? __ldg(&user4[i])
                               : __ldg(&item4[i - NUP1 * 16 + 16]);
    g_A16[i] = pack_half4(make_float2(v.x, v.y), make_float2(v.z, v.w));
}

// Single-pass decoupled-lookback scan -> g_ptr; self-clears g_cnt.
__global__ void scan_kernel() {
    int t = threadIdx.x, b = blockIdx.x;
    int lane = t & 31, wid = t >> 5;
    int gid = b * SCAN_B + t;

    int cnt = (gid < NROWS) ? g_cnt[gid] : 0;

    int incl = cnt;
    #pragma unroll
    for (int o = 1; o < 32; o <<= 1) {
        int n = __shfl_up_sync(0xffffffffu, incl, o);
        if (lane >= o) incl += n;
    }
    __shared__ int wsum[32];
    __shared__ int s_excl;
    if (lane == 31) wsum[wid] = incl;
    __syncthreads();
    if (wid == 0) {
        int v = wsum[lane];
        #pragma unroll
        for (int o = 1; o < 32; o <<= 1) {
            int n = __shfl_up_sync(0xffffffffu, v, o);
            if (lane >= o) v += n;
        }
        wsum[lane] = v;
    }
    __syncthreads();
    int block_incl = incl + (wid ? wsum[wid - 1] : 0);
    int total = wsum[31];

    if (t == 0) {
        if (b == 0) { g_look[0] = (2ull << 32) | (unsigned)total; s_excl = 0; }
        else          g_look[b] = (1ull << 32) | (unsigned)total;
    }
    if (b > 0 && wid == 0) {
        int excl = 0;
        int idx = b - 1;
        while (true) {
            int look = idx - lane;
            unsigned long long w; int st;
            do {
                w = g_look[look < 0 ? 0 : look];
                st = (look < 0) ? 2 : (int)(w >> 32);
            } while (__any_sync(0xffffffffu, st == 0));
            int val = (look < 0) ? 0 : (int)(unsigned)w;
            unsigned pm = __ballot_sync(0xffffffffu, (look >= 0) && st == 2);
            int contrib;
            if (pm) {
                int plane = __ffs(pm) - 1;
                contrib = (lane <= plane) ? val : 0;
            } else {
                contrib = val;
            }
            #pragma unroll
            for (int o = 16; o; o >>= 1)
                contrib += __shfl_down_sync(0xffffffffu, contrib, o);
            contrib = __shfl_sync(0xffffffffu, contrib, 0);
            excl += contrib;
            if (pm) break;
            idx -= 32;
        }
        if (lane == 0) {
            g_look[b] = (2ull << 32) | (unsigned)(excl + total);
            s_excl = excl;
        }
    }
    __syncthreads();
    if (gid < NROWS) {
        int ex = s_excl + block_incl - cnt;
        g_ptr[gid] = ex;
        g_cnt[gid] = 0;                        // self-clean for next replay
        if (gid == NROWS - 1) g_ptr[NROWS] = ex + cnt;
    }
}

// Atomic-free bucket; stores (col, half2(v,v)). Clears g_look.
__global__ void scatter_kernel(const int* __restrict__ rows,
                               const int* __restrict__ cols,
                               const float* __restrict__ vals, int nnz) {
    int e = blockIdx.x * blockDim.x + threadIdx.x;
    if (e < NB) g_look[e] = 0ull;
    if (e >= nnz) return;
    int pos = g_ptr[rows[e]] + g_rank[e];
    __half2 v2 = __half2half2(__float2half_rn(vals[e]));
    g_edge[pos] = make_uint2((unsigned)cols[e], *(unsigned*)&v2);
}

// Half-warp per row: 16 lanes x half4 (8B) = one 128B row.
// HFMA2 with 8 INDEPENDENT half2 accumulators (one pair per unroll slot);
// fp32 cross-slot reduction at row end. No converts in the hot loop.
__device__ __forceinline__ void row_spmv(const uint2* __restrict__ x,
                                         int s, int e, int l15,
                                         float2& s0, float2& s1) {
    __half2 z = __float2half2_rn(0.f);
    __half2 b0x = z, b0y = z, b1x = z, b1y = z;
    __half2 b2x = z, b2y = z, b3x = z, b3y = z;
    for (int j = s; j < e; j += 4) {
        uint2 e0 = __ldg(&g_edge[j]);
        uint2 e1 = (j + 1 < e) ? __ldg(&g_edge[j + 1]) : make_uint2(0u, 0u);
        uint2 e2 = (j + 2 < e) ? __ldg(&g_edge[j + 2]) : make_uint2(0u, 0u);
        uint2 e3 = (j + 3 < e) ? __ldg(&g_edge[j + 3]) : make_uint2(0u, 0u);
        uint2 g0 = __ldg(&x[(size_t)e0.x * 16 + l15]);
        uint2 g1 = __ldg(&x[(size_t)e1.x * 16 + l15]);
        uint2 g2 = __ldg(&x[(size_t)e2.x * 16 + l15]);
        uint2 g3 = __ldg(&x[(size_t)e3.x * 16 + l15]);
        __half2 v0 = *(__half2*)&e0.y;
        __half2 v1 = *(__half2*)&e1.y;
        __half2 v2 = *(__half2*)&e2.y;
        __half2 v3 = *(__half2*)&e3.y;
        b0x = __hfma2(v0, *(__half2*)&g0.x, b0x);
        b0y = __hfma2(v0, *(__half2*)&g0.y, b0y);
        b1x = __hfma2(v1, *(__half2*)&g1.x, b1x);
        b1y = __hfma2(v1, *(__half2*)&g1.y, b1y);
        b2x = __hfma2(v2, *(__half2*)&g2.x, b2x);
        b2y = __hfma2(v2, *(__half2*)&g2.y, b2y);
        b3x = __hfma2(v3, *(__half2*)&g3.x, b3x);
        b3y = __hfma2(v3, *(__half2*)&g3.y, b3y);
    }
    // fp32 cross-slot reduction
    float2 f0 = __half22float2(b0x), f1 = __half22float2(b1x);
    float2 f2 = __half22float2(b2x), f3 = __half22float2(b3x);
    s0 = make_float2((f0.x + f1.x) + (f2.x + f3.x),
                     (f0.y + f1.y) + (f2.y + f3.y));
    f0 = __half22float2(b0y); f1 = __half22float2(b1y);
    f2 = __half22float2(b2y); f3 = __half22float2(b3y);
    s1 = make_float2((f0.x + f1.x) + (f2.x + f3.x),
                     (f0.y + f1.y) + (f2.y + f3.y));
}

__global__ void spmm_mid(int layer) {
    int warp = (blockIdx.x * blockDim.x + threadIdx.x) >> 5;
    int lane = threadIdx.x & 31;
    int row  = warp * 2 + (lane >> 4);
    if (row >= NROWS) return;
    int l15 = lane & 15;
    const uint2* __restrict__ x = (layer == 0) ? g_A16 : g_B16;
    uint2*       __restrict__ y = (layer == 0) ? g_B16 : g_C16;
    float2 s0, s1;
    row_spmv(x, g_ptr[row], g_ptr[row + 1], l15, s0, s1);
    y[(size_t)row * 16 + l15] = pack_half4(s0, s1);
}

__global__ void spmm_final(const float4* __restrict__ user4,
                           const float4* __restrict__ item4,
                           float4* __restrict__ out) {
    int warp = (blockIdx.x * blockDim.x + threadIdx.x) >> 5;
    int lane = threadIdx.x & 31;
    int row  = warp * 2 + (lane >> 4);
    if (row >= NROWS) return;
    int l15 = lane & 15;
    float2 s0, s1;
    row_spmv(g_C16, g_ptr[row], g_ptr[row + 1], l15, s0, s1);
    size_t o = (size_t)row * 16 + l15;
    // layer-0 fp32 read directly from inputs (no staging copy)
    float4 a = (row < NUP1) ? __ldg(&user4[o])
                            : __ldg(&item4[(size_t)(row - NUP1 + 1) * 16 + l15]);
    float2 b0, b1, c0, c1;
    unpack_half4(g_B16[o], b0, b1);
    unpack_half4(g_C16[o], c0, c1);
    int outrow = (row < NUP1) ? row : row + 1;
    out[(size_t)outrow * 16 + l15] =
        make_float4((a.x + b0.x + c0.x + s0.x) * 0.25f,
                    (a.y + b0.y + c0.y + s0.y) * 0.25f,
                    (a.z + b1.x + c1.x + s1.x) * 0.25f,
                    (a.w + b1.y + c1.y + s1.y) * 0.25f);
    if (row == 0)
        out[(size_t)NUP1 * 16 + l15] = make_float4(0.f, 0.f, 0.f, 0.f);
}

extern "C" void kernel_launch(void* const* d_in, const int* in_sizes, int n_in,
                              void* d_out, int out_size) {
    const float4* user4 = (const float4*)d_in[0];
    const float4* item4 = (const float4*)d_in[1];
    const int*    rows  = (const int*)d_in[2];
    const int*    cols  = (const int*)d_in[3];
    const float*  vals  = (const float*)d_in[4];
    float4*       out   = (float4*)d_out;

    const int nnz = in_sizes[2];
    const int TB = 256;

    const int gInit = (NF4 + TB - 1) / TB;     // NF4 > NNZE, covers both
    const int gEdge = (nnz + TB - 1) / TB;
    const int nWarp = (NROWS + 1) / 2;
    const int gSpmm = (nWarp * 32 + TB - 1) / TB;

    init_kernel<<<gInit, TB>>>(user4, item4, rows, nnz);   // 0: init + hist/rank
    scan_kernel<<<NB, SCAN_B>>>();                         // 1
    scatter_kernel<<<gEdge, TB>>>(rows, cols, vals, nnz);  // 2 (atomic-free)
    spmm_mid<<<gSpmm, TB>>>(0);                            // 3  <- ncu lands here
    spmm_mid<<<gSpmm, TB>>>(1);                            // 4
    spmm_final<<<gSpmm, TB>>>(user4, item4, out);          // 5
}

// round 12
// speedup vs baseline: 1.5890x; 1.4084x over previous
#include <cuda_runtime.h>
#include <cuda_fp16.h>

#define NUP1    100001            // NUM_USERS + 1
#define NROWS   200001            // total nodes
#define NNZE    2000000
#define NF4     (NROWS * 16)      // 16 x half4 per node = 64 scalars
#define SCAN_B  1024
#define NB      ((NROWS + SCAN_B - 1) / SCAN_B)   // 196

// ---- static device scratch ----
__device__ uint2  g_A16[NF4];     // layer 0 fp16 (half4 packed)
__device__ uint2  g_B16[NF4];     // layer 1 fp16
__device__ uint2  g_C16[NF4];     // layer 2 fp16

__device__ int   g_cnt[NROWS];    // zero at entry; scan self-clears
__device__ int   g_rank[NNZE];    // per-edge rank within its row
__device__ int   g_ptr[NROWS + 1];
__device__ uint2 g_edge[NNZE];    // (col, fp32 val bits)
__device__ volatile unsigned long long g_look[NB];  // cleared by scatter

__device__ __forceinline__ uint2 pack_half4(float2 a, float2 b) {
    __half2 h0 = __floats2half2_rn(a.x, a.y);
    __half2 h1 = __floats2half2_rn(b.x, b.y);
    return make_uint2(*(unsigned*)&h0, *(unsigned*)&h1);
}
__device__ __forceinline__ void unpack_half4(uint2 u, float2& a, float2& b) {
    a = __half22float2(*(__half2*)&u.x);
    b = __half22float2(*(__half2*)&u.y);
}

// init fp16 mirror of embeddings AND histogram+rank (fused).
__global__ void init_kernel(const float4* __restrict__ user4,
                            const float4* __restrict__ item4,
                            const int* __restrict__ rows, int nnz) {
    int i = blockIdx.x * blockDim.x + threadIdx.x;
    if (i < nnz) g_rank[i] = atomicAdd(&g_cnt[rows[i]], 1);
    if (i >= NF4) return;
    float4 v = (i < NUP1 * 16) ? __ldg(&user4[i])
                               : __ldg(&item4[i - NUP1 * 16 + 16]);
    g_A16[i] = pack_half4(make_float2(v.x, v.y), make_float2(v.z, v.w));
}

// Single-pass decoupled-lookback scan -> g_ptr; self-clears g_cnt.
__global__ void scan_kernel() {
    int t = threadIdx.x, b = blockIdx.x;
    int lane = t & 31, wid = t >> 5;
    int gid = b * SCAN_B + t;

    int cnt = (gid < NROWS) ? g_cnt[gid] : 0;

    int incl = cnt;
    #pragma unroll
    for (int o = 1; o < 32; o <<= 1) {
        int n = __shfl_up_sync(0xffffffffu, incl, o);
        if (lane >= o) incl += n;
    }
    __shared__ int wsum[32];
    __shared__ int s_excl;
    if (lane == 31) wsum[wid] = incl;
    __syncthreads();
    if (wid == 0) {
        int v = wsum[lane];
        #pragma unroll
        for (int o = 1; o < 32; o <<= 1) {
            int n = __shfl_up_sync(0xffffffffu, v, o);
            if (lane >= o) v += n;
        }
        wsum[lane] = v;
    }
    __syncthreads();
    int block_incl = incl + (wid ? wsum[wid - 1] : 0);
    int total = wsum[31];

    if (t == 0) {
        if (b == 0) { g_look[0] = (2ull << 32) | (unsigned)total; s_excl = 0; }
        else          g_look[b] = (1ull << 32) | (unsigned)total;
    }
    if (b > 0 && wid == 0) {
        int excl = 0;
        int idx = b - 1;
        while (true) {
            int look = idx - lane;
            unsigned long long w; int st;
            do {
                w = g_look[look < 0 ? 0 : look];
                st = (look < 0) ? 2 : (int)(w >> 32);
            } while (__any_sync(0xffffffffu, st == 0));
            int val = (look < 0) ? 0 : (int)(unsigned)w;
            unsigned pm = __ballot_sync(0xffffffffu, (look >= 0) && st == 2);
            int contrib;
            if (pm) {
                int plane = __ffs(pm) - 1;
                contrib = (lane <= plane) ? val : 0;
            } else {
                contrib = val;
            }
            #pragma unroll
            for (int o = 16; o; o >>= 1)
                contrib += __shfl_down_sync(0xffffffffu, contrib, o);
            contrib = __shfl_sync(0xffffffffu, contrib, 0);
            excl += contrib;
            if (pm) break;
            idx -= 32;
        }
        if (lane == 0) {
            g_look[b] = (2ull << 32) | (unsigned)(excl + total);
            s_excl = excl;
        }
    }
    __syncthreads();
    if (gid < NROWS) {
        int ex = s_excl + block_incl - cnt;
        g_ptr[gid] = ex;
        g_cnt[gid] = 0;                        // self-clean for next replay
        if (gid == NROWS - 1) g_ptr[NROWS] = ex + cnt;
    }
}

// Atomic-free bucket: pos = ptr[row] + precomputed rank. Clears g_look.
__global__ void scatter_kernel(const int* __restrict__ rows,
                               const int* __restrict__ cols,
                               const float* __restrict__ vals, int nnz) {
    int e = blockIdx.x * blockDim.x + threadIdx.x;
    if (e < NB) g_look[e] = 0ull;
    if (e >= nnz) return;
    int pos = g_ptr[rows[e]] + g_rank[e];
    g_edge[pos] = make_uint2((unsigned)cols[e], (unsigned)__float_as_int(vals[e]));
}

// Half-warp per row: 16 lanes x half4 (8B) = one 128B row.
// fp16 gather, fp32 FFMA accumulation (R9 shape); xl pre-offset by lane.
__device__ __forceinline__ void row_spmv(const uint2* __restrict__ xl,
                                         int s, int e,
                                         float2& s0, float2& s1) {
    s0 = make_float2(0.f, 0.f);
    s1 = make_float2(0.f, 0.f);
    for (int j = s; j < e; j += 4) {
        uint2 e0 = __ldg(&g_edge[j]);
        uint2 e1 = (j + 1 < e) ? __ldg(&g_edge[j + 1]) : make_uint2(0u, 0u);
        uint2 e2 = (j + 2 < e) ? __ldg(&g_edge[j + 2]) : make_uint2(0u, 0u);
        uint2 e3 = (j + 3 < e) ? __ldg(&g_edge[j + 3]) : make_uint2(0u, 0u);
        uint2 g0 = __ldg(&xl[e0.x * 16u]);
        uint2 g1 = __ldg(&xl[e1.x * 16u]);
        uint2 g2 = __ldg(&xl[e2.x * 16u]);
        uint2 g3 = __ldg(&xl[e3.x * 16u]);
        float v0 = __uint_as_float(e0.y);
        float v1 = __uint_as_float(e1.y);
        float v2 = __uint_as_float(e2.y);
        float v3 = __uint_as_float(e3.y);
        float2 a, b;
        unpack_half4(g0, a, b);
        s0.x = fmaf(v0, a.x, s0.x); s0.y = fmaf(v0, a.y, s0.y);
        s1.x = fmaf(v0, b.x, s1.x); s1.y = fmaf(v0, b.y, s1.y);
        unpack_half4(g1, a, b);
        s0.x = fmaf(v1, a.x, s0.x); s0.y = fmaf(v1, a.y, s0.y);
        s1.x = fmaf(v1, b.x, s1.x); s1.y = fmaf(v1, b.y, s1.y);
        unpack_half4(g2, a, b);
        s0.x = fmaf(v2, a.x, s0.x); s0.y = fmaf(v2, a.y, s0.y);
        s1.x = fmaf(v2, b.x, s1.x); s1.y = fmaf(v2, b.y, s1.y);
        unpack_half4(g3, a, b);
        s0.x = fmaf(v3, a.x, s0.x); s0.y = fmaf(v3, a.y, s0.y);
        s1.x = fmaf(v3, b.x, s1.x); s1.y = fmaf(v3, b.y, s1.y);
    }
}

__global__ void spmm_mid(int layer) {
    int warp = (blockIdx.x * blockDim.x + threadIdx.x) >> 5;
    int lane = threadIdx.x & 31;
    int row  = warp * 2 + (lane >> 4);
    if (row >= NROWS) return;
    int l15 = lane & 15;
    const uint2* __restrict__ xl =
        ((layer == 0) ? g_A16 : g_B16) + l15;          // lane-offset base
    uint2* __restrict__ y = (layer == 0) ? g_B16 : g_C16;
    float2 s0, s1;
    row_spmv(xl, g_ptr[row], g_ptr[row + 1], s0, s1);
    y[(size_t)row * 16 + l15] = pack_half4(s0, s1);
}

__global__ void spmm_final(const float4* __restrict__ user4,
                           const float4* __restrict__ item4,
                           float4* __restrict__ out) {
    int warp = (blockIdx.x * blockDim.x + threadIdx.x) >> 5;
    int lane = threadIdx.x & 31;
    int row  = warp * 2 + (lane >> 4);
    if (row >= NROWS) return;
    int l15 = lane & 15;
    const uint2* __restrict__ xl = g_C16 + l15;
    float2 s0, s1;
    row_spmv(xl, g_ptr[row], g_ptr[row + 1], s0, s1);
    size_t o = (size_t)row * 16 + l15;
    // layer-0 fp32 read directly from inputs (no staging copy)
    float4 a = (row < NUP1) ? __ldg(&user4[o])
                            : __ldg(&item4[(size_t)(row - NUP1 + 1) * 16 + l15]);
    float2 b0, b1, c0, c1;
    unpack_half4(g_B16[o], b0, b1);
    unpack_half4(g_C16[o], c0, c1);
    int outrow = (row < NUP1) ? row : row + 1;
    out[(size_t)outrow * 16 + l15] =
        make_float4((a.x + b0.x + c0.x + s0.x) * 0.25f,
                    (a.y + b0.y + c0.y + s0.y) * 0.25f,
                    (a.z + b1.x + c1.x + s1.x) * 0.25f,
                    (a.w + b1.y + c1.y + s1.y) * 0.25f);
    if (row == 0)
        out[(size_t)NUP1 * 16 + l15] = make_float4(0.f, 0.f, 0.f, 0.f);
}

extern "C" void kernel_launch(void* const* d_in, const int* in_sizes, int n_in,
                              void* d_out, int out_size) {
    const float4* user4 = (const float4*)d_in[0];
    const float4* item4 = (const float4*)d_in[1];
    const int*    rows  = (const int*)d_in[2];
    const int*    cols  = (const int*)d_in[3];
    const float*  vals  = (const float*)d_in[4];
    float4*       out   = (float4*)d_out;

    const int nnz = in_sizes[2];
    const int TB = 256;

    const int gInit = (NF4 + TB - 1) / TB;     // NF4 > NNZE, covers both
    const int gEdge = (nnz + TB - 1) / TB;
    const int nWarp = (NROWS + 1) / 2;
    const int gSpmm = (nWarp * 32 + TB - 1) / TB;

    init_kernel<<<gInit, TB>>>(user4, item4, rows, nnz);   // 0: init + hist/rank
    scan_kernel<<<NB, SCAN_B>>>();                         // 1
    scatter_kernel<<<gEdge, TB>>>(rows, cols, vals, nnz);  // 2 (atomic-free)
    spmm_mid<<<gSpmm, TB>>>(0);                            // 3
    spmm_mid<<<gSpmm, TB>>>(1);                            // 4
    spmm_final<<<gSpmm, TB>>>(user4, item4, out);          // 5
}